// round 4
// baseline (speedup 1.0000x reference)
#include <cuda_runtime.h>
#include <cuda_bf16.h>
#include <math.h>

#define B_      2
#define S_      2048
#define HIDDEN_ 2048
#define NH      16
#define NKV     2
#define HD      256
#define ROT     64
#define MTOT    (B_ * S_)        // 4096 token rows
#define QDIM    (NH * HD)        // 4096
#define KVDIM   (NKV * HD)       // 512

// ---------------- scratch (static device arrays; no allocations) ----------------
__device__ float g_qg[(size_t)MTOT * 2 * QDIM];   // 4096 x 8192 (q | gate per head)
__device__ float g_q[(size_t)MTOT * QDIM];        // normalized+roped q
__device__ float g_gate[(size_t)MTOT * QDIM];     // raw gate logits
__device__ float g_k[(size_t)MTOT * KVDIM];       // k (normalized+roped in place)
__device__ float g_v[(size_t)MTOT * KVDIM];
__device__ float g_attn[(size_t)MTOT * QDIM];     // gated attention output

// ---------------- SGEMM: C[M,N] = A[M,K] * B[N,K]^T (all row-major) -------------
// M,N multiples of 128; K multiple of 16. Register-staged double buffering.
__global__ __launch_bounds__(256) void sgemm_nt(
    const float* __restrict__ A, const float* __restrict__ Bm,
    float* __restrict__ C, int M, int N, int K)
{
    constexpr int BM = 128, BN = 128, BK = 16;
    __shared__ float As[BK][BM];
    __shared__ float Bs[BK][BN];

    const int tid = threadIdx.x;
    const int tx = tid & 15, ty = tid >> 4;
    const int row0 = blockIdx.y * BM;
    const int col0 = blockIdx.x * BN;

    // per-thread load coordinates (2 float4 each for A and B)
    int lr[2], lc[2];
#pragma unroll
    for (int l = 0; l < 2; l++) {
        int qi = tid + l * 256;
        lr[l] = qi >> 2;
        lc[l] = (qi & 3) << 2;
    }

    float acc[8][8];
#pragma unroll
    for (int i = 0; i < 8; i++)
#pragma unroll
        for (int j = 0; j < 8; j++) acc[i][j] = 0.f;

    float4 pa[2], pb[2];
    // prefetch tile 0
#pragma unroll
    for (int l = 0; l < 2; l++) {
        pa[l] = *(const float4*)(A  + (size_t)(row0 + lr[l]) * K + lc[l]);
        pb[l] = *(const float4*)(Bm + (size_t)(col0 + lr[l]) * K + lc[l]);
    }

    for (int k0 = 0; k0 < K; k0 += BK) {
        // commit staged registers to smem
#pragma unroll
        for (int l = 0; l < 2; l++) {
            int r = lr[l], c4 = lc[l];
            As[c4 + 0][r] = pa[l].x; As[c4 + 1][r] = pa[l].y;
            As[c4 + 2][r] = pa[l].z; As[c4 + 3][r] = pa[l].w;
            Bs[c4 + 0][r] = pb[l].x; Bs[c4 + 1][r] = pb[l].y;
            Bs[c4 + 2][r] = pb[l].z; Bs[c4 + 3][r] = pb[l].w;
        }
        __syncthreads();

        // prefetch next tile while computing this one
        if (k0 + BK < K) {
#pragma unroll
            for (int l = 0; l < 2; l++) {
                pa[l] = *(const float4*)(A  + (size_t)(row0 + lr[l]) * K + k0 + BK + lc[l]);
                pb[l] = *(const float4*)(Bm + (size_t)(col0 + lr[l]) * K + k0 + BK + lc[l]);
            }
        }

#pragma unroll
        for (int kk = 0; kk < BK; kk++) {
            float a[8], b[8];
            *(float4*)&a[0] = *(const float4*)&As[kk][ty * 8];
            *(float4*)&a[4] = *(const float4*)&As[kk][ty * 8 + 4];
            *(float4*)&b[0] = *(const float4*)&Bs[kk][tx * 8];
            *(float4*)&b[4] = *(const float4*)&Bs[kk][tx * 8 + 4];
#pragma unroll
            for (int i = 0; i < 8; i++)
#pragma unroll
                for (int j = 0; j < 8; j++) acc[i][j] += a[i] * b[j];
        }
        __syncthreads();
    }
#pragma unroll
    for (int i = 0; i < 8; i++) {
        size_t crow = (size_t)(row0 + ty * 8 + i) * N + col0 + tx * 8;
        float4 v0 = make_float4(acc[i][0], acc[i][1], acc[i][2], acc[i][3]);
        float4 v1 = make_float4(acc[i][4], acc[i][5], acc[i][6], acc[i][7]);
        *(float4*)(C + crow) = v0;
        *(float4*)(C + crow + 4) = v1;
    }
}

// ---------------- per-head RMSNorm + RoPE -----------------
__global__ __launch_bounds__(256) void qnorm_rope(
    const float* __restrict__ qg, const float* __restrict__ cosb,
    const float* __restrict__ sinb, const float* __restrict__ w,
    float* __restrict__ qout, float* __restrict__ gateout)
{
    const int h = blockIdx.x & (NH - 1);
    const int m = blockIdx.x >> 4;
    const int tid = threadIdx.x;
    const float* src = qg + (size_t)m * (2 * QDIM) + h * (2 * HD);

    float x = src[tid];
    float v2 = x * x;
#pragma unroll
    for (int off = 16; off; off >>= 1)
        v2 += __shfl_xor_sync(0xffffffffu, v2, off);
    __shared__ float red[8];
    if ((tid & 31) == 0) red[tid >> 5] = v2;
    __syncthreads();
    float tot = 0.f;
#pragma unroll
    for (int wi = 0; wi < 8; wi++) tot += red[wi];
    const float inv = rsqrtf(tot * (1.0f / HD) + 1e-6f);
    float xn = x * inv * w[tid];

    __shared__ float sh[HD];
    sh[tid] = xn;
    __syncthreads();
    float outv = xn;
    if (tid < ROT) {
        float c = cosb[(size_t)m * ROT + tid];
        float s = sinb[(size_t)m * ROT + tid];
        float rh = (tid < ROT / 2) ? -sh[tid + ROT / 2] : sh[tid - ROT / 2];
        outv = xn * c + rh * s;
    }
    size_t di = (size_t)m * QDIM + h * HD + tid;
    qout[di] = outv;
    gateout[di] = src[HD + tid];
}

__global__ __launch_bounds__(256) void knorm_rope(
    float* __restrict__ kbuf, const float* __restrict__ cosb,
    const float* __restrict__ sinb, const float* __restrict__ w)
{
    const int h = blockIdx.x & (NKV - 1);
    const int m = blockIdx.x >> 1;
    const int tid = threadIdx.x;
    float* src = kbuf + (size_t)m * KVDIM + h * HD;

    float x = src[tid];
    float v2 = x * x;
#pragma unroll
    for (int off = 16; off; off >>= 1)
        v2 += __shfl_xor_sync(0xffffffffu, v2, off);
    __shared__ float red[8];
    if ((tid & 31) == 0) red[tid >> 5] = v2;
    __syncthreads();
    float tot = 0.f;
#pragma unroll
    for (int wi = 0; wi < 8; wi++) tot += red[wi];
    const float inv = rsqrtf(tot * (1.0f / HD) + 1e-6f);
    float xn = x * inv * w[tid];

    __shared__ float sh[HD];
    sh[tid] = xn;
    __syncthreads();
    float outv = xn;
    if (tid < ROT) {
        float c = cosb[(size_t)m * ROT + tid];
        float s = sinb[(size_t)m * ROT + tid];
        float rh = (tid < ROT / 2) ? -sh[tid + ROT / 2] : sh[tid - ROT / 2];
        outv = xn * c + rh * s;
    }
    src[tid] = outv;
}

// ---------------- flash attention (fp32), gate fused in epilogue ----------------
#define QT   64
#define KT   64
#define PADR 257     // row stride (floats) for 256-wide tiles: odd -> conflict-free
#define SSTR 65      // row stride for 64-wide S tile
#define ATTN_SMEM ((3 * QT * PADR + QT * SSTR) * (int)sizeof(float))  // 214,016 B

__global__ __launch_bounds__(256) void attn_kernel(
    const float* __restrict__ q, const float* __restrict__ k,
    const float* __restrict__ v, const float* __restrict__ gate,
    float* __restrict__ out)
{
    extern __shared__ float smem[];
    float* Qs = smem;                  // QT x PADR
    float* Ks = Qs + QT * PADR;        // KT x PADR
    float* Vs = Ks + QT * PADR;        // KT x PADR
    float* Ss = Vs + QT * PADR;        // QT x SSTR

    const int qt = blockIdx.x;
    const int h = blockIdx.y;
    const int b = blockIdx.z;
    const int kv = h >> 3;             // N_HEADS / N_KV = 8
    const int tid = threadIdx.x;
    const int tr = tid >> 4;
    const int tc = tid & 15;
    const int q0 = qt * QT;
    const float scale = 0.0625f;       // 1/sqrt(256)

    for (int idx = tid; idx < QT * HD; idx += 256) {
        int r = idx >> 8, c = idx & 255;
        Qs[r * PADR + c] = q[(size_t)(b * S_ + q0 + r) * QDIM + h * HD + c];
    }

    float o[4][16];
#pragma unroll
    for (int i = 0; i < 4; i++)
#pragma unroll
        for (int c = 0; c < 16; c++) o[i][c] = 0.f;
    float m_r[4] = {-1e30f, -1e30f, -1e30f, -1e30f};
    float l_r[4] = {0.f, 0.f, 0.f, 0.f};

    for (int kt = 0; kt <= qt; kt++) {
        const int k0 = kt * KT;
        __syncthreads();
        for (int idx = tid; idx < KT * HD; idx += 256) {
            int r = idx >> 8, c = idx & 255;
            size_t gi = (size_t)(b * S_ + k0 + r) * KVDIM + kv * HD + c;
            Ks[r * PADR + c] = k[gi];
            Vs[r * PADR + c] = v[gi];
        }
        __syncthreads();

        float s[4][4];
#pragma unroll
        for (int i = 0; i < 4; i++)
#pragma unroll
            for (int j = 0; j < 4; j++) s[i][j] = 0.f;
#pragma unroll 8
        for (int d = 0; d < HD; d++) {
            float qv[4], kvv[4];
#pragma unroll
            for (int i = 0; i < 4; i++) qv[i] = Qs[(tr * 4 + i) * PADR + d];
#pragma unroll
            for (int j = 0; j < 4; j++) kvv[j] = Ks[(tc + 16 * j) * PADR + d];
#pragma unroll
            for (int i = 0; i < 4; i++)
#pragma unroll
                for (int j = 0; j < 4; j++) s[i][j] += qv[i] * kvv[j];
        }

#pragma unroll
        for (int i = 0; i < 4; i++) {
            const int qpos = q0 + tr * 4 + i;
            float tmax = -1e30f;
#pragma unroll
            for (int j = 0; j < 4; j++) {
                int kpos = k0 + tc + 16 * j;
                s[i][j] = (kpos <= qpos) ? s[i][j] * scale : -1e30f;
                tmax = fmaxf(tmax, s[i][j]);
            }
#pragma unroll
            for (int off = 1; off < 16; off <<= 1)
                tmax = fmaxf(tmax, __shfl_xor_sync(0xffffffffu, tmax, off));
            float nm = fmaxf(m_r[i], tmax);
            float alpha = __expf(m_r[i] - nm);
            float rs = 0.f;
#pragma unroll
            for (int j = 0; j < 4; j++) {
                float p = __expf(s[i][j] - nm);
                Ss[(tr * 4 + i) * SSTR + tc + 16 * j] = p;
                rs += p;
            }
#pragma unroll
            for (int off = 1; off < 16; off <<= 1)
                rs += __shfl_xor_sync(0xffffffffu, rs, off);
            l_r[i] = l_r[i] * alpha + rs;
            m_r[i] = nm;
#pragma unroll
            for (int c = 0; c < 16; c++) o[i][c] *= alpha;
        }
        __syncthreads();

#pragma unroll 4
        for (int kk = 0; kk < KT; kk++) {
            float p[4];
#pragma unroll
            for (int i = 0; i < 4; i++) p[i] = Ss[(tr * 4 + i) * SSTR + kk];
#pragma unroll
            for (int c = 0; c < 16; c++) {
                float vv = Vs[kk * PADR + tc + 16 * c];
#pragma unroll
                for (int i = 0; i < 4; i++) o[i][c] += p[i] * vv;
            }
        }
    }

#pragma unroll
    for (int i = 0; i < 4; i++) {
        const int qpos = q0 + tr * 4 + i;
        const size_t base = (size_t)(b * S_ + qpos) * QDIM + h * HD;
        const float linv = 1.0f / l_r[i];
#pragma unroll
        for (int c = 0; c < 16; c++) {
            int col = tc + 16 * c;
            float g = gate[base + col];
            float sg = 1.0f / (1.0f + __expf(-g));
            out[base + col] = o[i][c] * linv * sg;
        }
    }
}

// ---------------- launch ----------------
extern "C" void kernel_launch(void* const* d_in, const int* in_sizes, int n_in,
                              void* d_out, int out_size)
{
    (void)in_sizes; (void)n_in; (void)out_size;
    const float* hidden = (const float*)d_in[0];
    const float* cosb   = (const float*)d_in[1];
    const float* sinb   = (const float*)d_in[2];
    const float* Wq     = (const float*)d_in[3];
    const float* Wk     = (const float*)d_in[4];
    const float* Wv     = (const float*)d_in[5];
    const float* Wo     = (const float*)d_in[6];
    const float* qw     = (const float*)d_in[7];
    const float* kw     = (const float*)d_in[8];
    float* out = (float*)d_out;

    float *qg, *q, *gate, *k, *v, *attn;
    cudaGetSymbolAddress((void**)&qg,   g_qg);
    cudaGetSymbolAddress((void**)&q,    g_q);
    cudaGetSymbolAddress((void**)&gate, g_gate);
    cudaGetSymbolAddress((void**)&k,    g_k);
    cudaGetSymbolAddress((void**)&v,    g_v);
    cudaGetSymbolAddress((void**)&attn, g_attn);

    static bool attr_set = false;
    if (!attr_set) {
        cudaFuncSetAttribute(attn_kernel,
                             cudaFuncAttributeMaxDynamicSharedMemorySize,
                             ATTN_SMEM);
        attr_set = true;
    }

    dim3 blk(256);
    // projections
    sgemm_nt<<<dim3((2 * QDIM) / 128, MTOT / 128), blk>>>(hidden, Wq, qg, MTOT, 2 * QDIM, HIDDEN_);
    sgemm_nt<<<dim3(KVDIM / 128, MTOT / 128), blk>>>(hidden, Wk, k, MTOT, KVDIM, HIDDEN_);
    sgemm_nt<<<dim3(KVDIM / 128, MTOT / 128), blk>>>(hidden, Wv, v, MTOT, KVDIM, HIDDEN_);
    // norm + rope
    qnorm_rope<<<MTOT * NH, 256>>>(qg, cosb, sinb, qw, q, gate);
    knorm_rope<<<MTOT * NKV, 256>>>(k, cosb, sinb, kw);
    // attention (gate fused)
    attn_kernel<<<dim3(S_ / QT, NH, B_), 256, ATTN_SMEM>>>(q, k, v, gate, attn);
    // output projection (K = QDIM = 4096, attn/Wo row width)
    sgemm_nt<<<dim3(HIDDEN_ / 128, MTOT / 128), blk>>>(attn, Wo, out, MTOT, HIDDEN_, QDIM);
}

// round 16
// speedup vs baseline: 1.5218x; 1.5218x over previous
#include <cuda_runtime.h>
#include <cuda_bf16.h>
#include <cstdint>
#include <math.h>

#define B_      2
#define S_      2048
#define HIDDEN_ 2048
#define NH      16
#define NKV     2
#define HD      256
#define ROT     64
#define MTOT    (B_ * S_)
#define QDIM    (NH * HD)
#define KVDIM   (NKV * HD)

// ---------------- scratch ----------------
__device__ float g_qg[(size_t)MTOT * 2 * QDIM];
__device__ float g_q[(size_t)MTOT * QDIM];
__device__ float g_gate[(size_t)MTOT * QDIM];
__device__ float g_k[(size_t)MTOT * KVDIM];
__device__ float g_v[(size_t)MTOT * KVDIM];
__device__ float g_attn[(size_t)MTOT * QDIM];

__device__ __nv_bfloat16 g_hb[(size_t)MTOT * 3 * HIDDEN_];
__device__ __nv_bfloat16 g_wqb[(size_t)2 * QDIM * 3 * HIDDEN_];
__device__ __nv_bfloat16 g_wkb[(size_t)KVDIM * 3 * HIDDEN_];
__device__ __nv_bfloat16 g_wvb[(size_t)KVDIM * 3 * HIDDEN_];
__device__ __nv_bfloat16 g_wob[(size_t)HIDDEN_ * 3 * QDIM];
__device__ __nv_bfloat16 g_ab[(size_t)MTOT * 3 * QDIM];

// ---------------- split-3: X[R][K] fp32 -> Y[R][3K] bf16 ----------------
// modeA=1: [hi, lo, hi]   modeA=0: [hi, hi, lo]
__global__ __launch_bounds__(256) void split3(
    const float* __restrict__ X, __nv_bfloat16* __restrict__ Y, int K, int modeA)
{
    const int kk = blockIdx.x * 256 + threadIdx.x;
    const size_t rr = blockIdx.y;
    float x = X[rr * K + kk];
    __nv_bfloat16 hi = __float2bfloat16_rn(x);
    __nv_bfloat16 lo = __float2bfloat16_rn(x - __bfloat162float(hi));
    size_t base = rr * (size_t)(3 * K) + kk;
    Y[base] = hi;
    if (modeA) {
        Y[base + K] = lo;
        Y[base + 2 * K] = hi;
    } else {
        Y[base + K] = hi;
        Y[base + 2 * K] = lo;
    }
}

// ---------------- bf16 tensor-core GEMM: C[M,N] = A[M,K] * B[N,K]^T --------------
#define LDSB 40

__global__ __launch_bounds__(256) void hgemm_nt(
    const __nv_bfloat16* __restrict__ A, const __nv_bfloat16* __restrict__ Bm,
    float* __restrict__ C, int M, int N, int K)
{
    __shared__ __nv_bfloat16 As[128 * LDSB];
    __shared__ __nv_bfloat16 Bs[128 * LDSB];

    const int tid = threadIdx.x;
    const int lane = tid & 31;
    const int wrp = tid >> 5;
    const int wm = (wrp & 1) * 64;
    const int wn = (wrp >> 1) * 32;
    const int row0 = blockIdx.y * 128;
    const int col0 = blockIdx.x * 128;

    const int lr0 = tid >> 2;
    const int lc0 = (tid & 3) * 8;
    const int lr1 = lr0 + 64;

    uint4 pa0, pa1, pb0, pb1;
    pa0 = *(const uint4*)(A + (size_t)(row0 + lr0) * K + lc0);
    pa1 = *(const uint4*)(A + (size_t)(row0 + lr1) * K + lc0);
    pb0 = *(const uint4*)(Bm + (size_t)(col0 + lr0) * K + lc0);
    pb1 = *(const uint4*)(Bm + (size_t)(col0 + lr1) * K + lc0);

    float acc[4][4][4];
#pragma unroll
    for (int i = 0; i < 4; i++) {
#pragma unroll
        for (int j = 0; j < 4; j++) {
#pragma unroll
            for (int t = 0; t < 4; t++) {
                acc[i][j][t] = 0.0f;
            }
        }
    }

    for (int k0 = 0; k0 < K; k0 += 32) {
        *(uint4*)(As + lr0 * LDSB + lc0) = pa0;
        *(uint4*)(As + lr1 * LDSB + lc0) = pa1;
        *(uint4*)(Bs + lr0 * LDSB + lc0) = pb0;
        *(uint4*)(Bs + lr1 * LDSB + lc0) = pb1;
        __syncthreads();

        if (k0 + 32 < K) {
            pa0 = *(const uint4*)(A + (size_t)(row0 + lr0) * K + k0 + 32 + lc0);
            pa1 = *(const uint4*)(A + (size_t)(row0 + lr1) * K + k0 + 32 + lc0);
            pb0 = *(const uint4*)(Bm + (size_t)(col0 + lr0) * K + k0 + 32 + lc0);
            pb1 = *(const uint4*)(Bm + (size_t)(col0 + lr1) * K + k0 + 32 + lc0);
        }

#pragma unroll
        for (int ks = 0; ks < 2; ks++) {
            uint32_t fa[4][4];
            uint32_t fb[4][2];
#pragma unroll
            for (int mt = 0; mt < 4; mt++) {
                uint32_t addr = (uint32_t)__cvta_generic_to_shared(
                    As + (wm + mt * 16 + (lane & 15)) * LDSB + ks * 16 + (lane >> 4) * 8);
                asm volatile(
                    "ldmatrix.sync.aligned.m8n8.x4.shared.b16 {%0,%1,%2,%3}, [%4];"
                    : "=r"(fa[mt][0]), "=r"(fa[mt][1]), "=r"(fa[mt][2]), "=r"(fa[mt][3])
                    : "r"(addr));
            }
#pragma unroll
            for (int bp = 0; bp < 2; bp++) {
                uint32_t addr = (uint32_t)__cvta_generic_to_shared(
                    Bs + (wn + bp * 16 + (lane & 7) + ((lane >> 4) << 3)) * LDSB
                       + ks * 16 + (((lane >> 3) & 1) << 3));
                uint32_t t0, t1, t2, t3;
                asm volatile(
                    "ldmatrix.sync.aligned.m8n8.x4.shared.b16 {%0,%1,%2,%3}, [%4];"
                    : "=r"(t0), "=r"(t1), "=r"(t2), "=r"(t3)
                    : "r"(addr));
                fb[bp * 2][0] = t0;
                fb[bp * 2][1] = t1;
                fb[bp * 2 + 1][0] = t2;
                fb[bp * 2 + 1][1] = t3;
            }
#pragma unroll
            for (int mt = 0; mt < 4; mt++) {
#pragma unroll
                for (int nt = 0; nt < 4; nt++) {
                    asm volatile(
                        "mma.sync.aligned.m16n8k16.row.col.f32.bf16.bf16.f32 "
                        "{%0,%1,%2,%3}, {%4,%5,%6,%7}, {%8,%9}, {%0,%1,%2,%3};"
                        : "+f"(acc[mt][nt][0]), "+f"(acc[mt][nt][1]),
                          "+f"(acc[mt][nt][2]), "+f"(acc[mt][nt][3])
                        : "r"(fa[mt][0]), "r"(fa[mt][1]), "r"(fa[mt][2]), "r"(fa[mt][3]),
                          "r"(fb[nt][0]), "r"(fb[nt][1]));
                }
            }
        }
        __syncthreads();
    }

#pragma unroll
    for (int mt = 0; mt < 4; mt++) {
        const int r = row0 + wm + mt * 16 + (lane >> 2);
#pragma unroll
        for (int nt = 0; nt < 4; nt++) {
            const int c = col0 + wn + nt * 8 + (lane & 3) * 2;
            float2 v0;
            float2 v1;
            v0.x = acc[mt][nt][0];
            v0.y = acc[mt][nt][1];
            v1.x = acc[mt][nt][2];
            v1.y = acc[mt][nt][3];
            *(float2*)(C + (size_t)r * N + c) = v0;
            *(float2*)(C + (size_t)(r + 8) * N + c) = v1;
        }
    }
}

// ---------------- per-head RMSNorm + RoPE -----------------
__global__ __launch_bounds__(256) void qnorm_rope(
    const float* __restrict__ qg, const float* __restrict__ cosb,
    const float* __restrict__ sinb, const float* __restrict__ w,
    float* __restrict__ qout, float* __restrict__ gateout)
{
    const int h = blockIdx.x & (NH - 1);
    const int m = blockIdx.x >> 4;
    const int tid = threadIdx.x;
    const float* src = qg + (size_t)m * (2 * QDIM) + h * (2 * HD);

    float x = src[tid];
    float v2 = x * x;
#pragma unroll
    for (int off = 16; off; off >>= 1)
        v2 += __shfl_xor_sync(0xffffffffu, v2, off);
    __shared__ float red[8];
    if ((tid & 31) == 0) red[tid >> 5] = v2;
    __syncthreads();
    float tot = 0.f;
#pragma unroll
    for (int wi = 0; wi < 8; wi++) tot += red[wi];
    const float inv = rsqrtf(tot * (1.0f / HD) + 1e-6f);
    float xn = x * inv * w[tid];

    __shared__ float sh[HD];
    sh[tid] = xn;
    __syncthreads();
    float outv = xn;
    if (tid < ROT) {
        float c = cosb[(size_t)m * ROT + tid];
        float s = sinb[(size_t)m * ROT + tid];
        float rh = (tid < ROT / 2) ? -sh[tid + ROT / 2] : sh[tid - ROT / 2];
        outv = xn * c + rh * s;
    }
    size_t di = (size_t)m * QDIM + h * HD + tid;
    qout[di] = outv;
    gateout[di] = src[HD + tid];
}

__global__ __launch_bounds__(256) void knorm_rope(
    float* __restrict__ kbuf, const float* __restrict__ cosb,
    const float* __restrict__ sinb, const float* __restrict__ w)
{
    const int h = blockIdx.x & (NKV - 1);
    const int m = blockIdx.x >> 1;
    const int tid = threadIdx.x;
    float* src = kbuf + (size_t)m * KVDIM + h * HD;

    float x = src[tid];
    float v2 = x * x;
#pragma unroll
    for (int off = 16; off; off >>= 1)
        v2 += __shfl_xor_sync(0xffffffffu, v2, off);
    __shared__ float red[8];
    if ((tid & 31) == 0) red[tid >> 5] = v2;
    __syncthreads();
    float tot = 0.f;
#pragma unroll
    for (int wi = 0; wi < 8; wi++) tot += red[wi];
    const float inv = rsqrtf(tot * (1.0f / HD) + 1e-6f);
    float xn = x * inv * w[tid];

    __shared__ float sh[HD];
    sh[tid] = xn;
    __syncthreads();
    float outv = xn;
    if (tid < ROT) {
        float c = cosb[(size_t)m * ROT + tid];
        float s = sinb[(size_t)m * ROT + tid];
        float rh = (tid < ROT / 2) ? -sh[tid + ROT / 2] : sh[tid - ROT / 2];
        outv = xn * c + rh * s;
    }
    src[tid] = outv;
}

// ---------------- flash attention (fp32), gate fused ----------------
#define QT   64
#define KT   64
#define PADR 257
#define SSTR 65
#define ATTN_SMEM ((3 * QT * PADR + QT * SSTR) * (int)sizeof(float))

__global__ __launch_bounds__(256) void attn_kernel(
    const float* __restrict__ q, const float* __restrict__ k,
    const float* __restrict__ v, const float* __restrict__ gate,
    float* __restrict__ out)
{
    extern __shared__ float smem[];
    float* Qs = smem;
    float* Ks = Qs + QT * PADR;
    float* Vs = Ks + QT * PADR;
    float* Ss = Vs + QT * PADR;

    const int qt = blockIdx.x;
    const int h = blockIdx.y;
    const int b = blockIdx.z;
    const int kv = h >> 3;
    const int tid = threadIdx.x;
    const int tr = tid >> 4;
    const int tc = tid & 15;
    const int q0 = qt * QT;
    const float scale = 0.0625f;

    for (int idx = tid; idx < QT * HD; idx += 256) {
        int r = idx >> 8, c = idx & 255;
        Qs[r * PADR + c] = q[(size_t)(b * S_ + q0 + r) * QDIM + h * HD + c];
    }

    float o[4][16];
#pragma unroll
    for (int i = 0; i < 4; i++)
#pragma unroll
        for (int c = 0; c < 16; c++) o[i][c] = 0.f;
    float m_r[4] = {-1e30f, -1e30f, -1e30f, -1e30f};
    float l_r[4] = {0.f, 0.f, 0.f, 0.f};

    for (int kt = 0; kt <= qt; kt++) {
        const int k0 = kt * KT;
        __syncthreads();
        for (int idx = tid; idx < KT * HD; idx += 256) {
            int r = idx >> 8, c = idx & 255;
            size_t gi = (size_t)(b * S_ + k0 + r) * KVDIM + kv * HD + c;
            Ks[r * PADR + c] = k[gi];
            Vs[r * PADR + c] = v[gi];
        }
        __syncthreads();

        float s[4][4];
#pragma unroll
        for (int i = 0; i < 4; i++)
#pragma unroll
            for (int j = 0; j < 4; j++) s[i][j] = 0.f;
#pragma unroll 8
        for (int d = 0; d < HD; d++) {
            float qv[4], kvv[4];
#pragma unroll
            for (int i = 0; i < 4; i++) qv[i] = Qs[(tr * 4 + i) * PADR + d];
#pragma unroll
            for (int j = 0; j < 4; j++) kvv[j] = Ks[(tc + 16 * j) * PADR + d];
#pragma unroll
            for (int i = 0; i < 4; i++)
#pragma unroll
                for (int j = 0; j < 4; j++) s[i][j] += qv[i] * kvv[j];
        }

#pragma unroll
        for (int i = 0; i < 4; i++) {
            const int qpos = q0 + tr * 4 + i;
            float tmax = -1e30f;
#pragma unroll
            for (int j = 0; j < 4; j++) {
                int kpos = k0 + tc + 16 * j;
                s[i][j] = (kpos <= qpos) ? s[i][j] * scale : -1e30f;
                tmax = fmaxf(tmax, s[i][j]);
            }
#pragma unroll
            for (int off = 1; off < 16; off <<= 1)
                tmax = fmaxf(tmax, __shfl_xor_sync(0xffffffffu, tmax, off));
            float nm = fmaxf(m_r[i], tmax);
            float alpha = __expf(m_r[i] - nm);
            float rs = 0.f;
#pragma unroll
            for (int j = 0; j < 4; j++) {
                float p = __expf(s[i][j] - nm);
                Ss[(tr * 4 + i) * SSTR + tc + 16 * j] = p;
                rs += p;
            }
#pragma unroll
            for (int off = 1; off < 16; off <<= 1)
                rs += __shfl_xor_sync(0xffffffffu, rs, off);
            l_r[i] = l_r[i] * alpha + rs;
            m_r[i] = nm;
#pragma unroll
            for (int c = 0; c < 16; c++) o[i][c] *= alpha;
        }
        __syncthreads();

#pragma unroll 4
        for (int kk = 0; kk < KT; kk++) {
            float p[4];
#pragma unroll
            for (int i = 0; i < 4; i++) p[i] = Ss[(tr * 4 + i) * SSTR + kk];
#pragma unroll
            for (int c = 0; c < 16; c++) {
                float vv = Vs[kk * PADR + tc + 16 * c];
#pragma unroll
                for (int i = 0; i < 4; i++) o[i][c] += p[i] * vv;
            }
        }
    }

#pragma unroll
    for (int i = 0; i < 4; i++) {
        const int qpos = q0 + tr * 4 + i;
        const size_t base = (size_t)(b * S_ + qpos) * QDIM + h * HD;
        const float linv = 1.0f / l_r[i];
#pragma unroll
        for (int c = 0; c < 16; c++) {
            int col = tc + 16 * c;
            float g = gate[base + col];
            float sg = 1.0f / (1.0f + __expf(-g));
            out[base + col] = o[i][c] * linv * sg;
        }
    }
}

// ---------------- launch ----------------
extern "C" void kernel_launch(void* const* d_in, const int* in_sizes, int n_in,
                              void* d_out, int out_size)
{
    (void)in_sizes; (void)n_in; (void)out_size;
    const float* hidden = (const float*)d_in[0];
    const float* cosb   = (const float*)d_in[1];
    const float* sinb   = (const float*)d_in[2];
    const float* Wq     = (const float*)d_in[3];
    const float* Wk     = (const float*)d_in[4];
    const float* Wv     = (const float*)d_in[5];
    const float* Wo     = (const float*)d_in[6];
    const float* qw     = (const float*)d_in[7];
    const float* kw     = (const float*)d_in[8];
    float* out = (float*)d_out;

    float* qg = 0;
    float* q = 0;
    float* gate = 0;
    float* k = 0;
    float* v = 0;
    float* attn = 0;
    __nv_bfloat16* hb = 0;
    __nv_bfloat16* wqb = 0;
    __nv_bfloat16* wkb = 0;
    __nv_bfloat16* wvb = 0;
    __nv_bfloat16* wob = 0;
    __nv_bfloat16* ab = 0;
    cudaGetSymbolAddress((void**)&qg, g_qg);
    cudaGetSymbolAddress((void**)&q, g_q);
    cudaGetSymbolAddress((void**)&gate, g_gate);
    cudaGetSymbolAddress((void**)&k, g_k);
    cudaGetSymbolAddress((void**)&v, g_v);
    cudaGetSymbolAddress((void**)&attn, g_attn);
    cudaGetSymbolAddress((void**)&hb, g_hb);
    cudaGetSymbolAddress((void**)&wqb, g_wqb);
    cudaGetSymbolAddress((void**)&wkb, g_wkb);
    cudaGetSymbolAddress((void**)&wvb, g_wvb);
    cudaGetSymbolAddress((void**)&wob, g_wob);
    cudaGetSymbolAddress((void**)&ab, g_ab);

    static bool attr_set = false;
    if (!attr_set) {
        cudaFuncSetAttribute(attn_kernel,
                             cudaFuncAttributeMaxDynamicSharedMemorySize,
                             ATTN_SMEM);
        attr_set = true;
    }

    dim3 blk(256);

    split3<<<dim3(HIDDEN_ / 256, MTOT), blk>>>(hidden, hb, HIDDEN_, 1);
    split3<<<dim3(HIDDEN_ / 256, 2 * QDIM), blk>>>(Wq, wqb, HIDDEN_, 0);
    split3<<<dim3(HIDDEN_ / 256, KVDIM), blk>>>(Wk, wkb, HIDDEN_, 0);
    split3<<<dim3(HIDDEN_ / 256, KVDIM), blk>>>(Wv, wvb, HIDDEN_, 0);
    split3<<<dim3(QDIM / 256, HIDDEN_), blk>>>(Wo, wob, QDIM, 0);

    hgemm_nt<<<dim3((2 * QDIM) / 128, MTOT / 128), blk>>>(hb, wqb, qg, MTOT, 2 * QDIM, 3 * HIDDEN_);
    hgemm_nt<<<dim3(KVDIM / 128, MTOT / 128), blk>>>(hb, wkb, k, MTOT, KVDIM, 3 * HIDDEN_);
    hgemm_nt<<<dim3(KVDIM / 128, MTOT / 128), blk>>>(hb, wvb, v, MTOT, KVDIM, 3 * HIDDEN_);

    qnorm_rope<<<MTOT * NH, 256>>>(qg, cosb, sinb, qw, q, gate);
    knorm_rope<<<MTOT * NKV, 256>>>(k, cosb, sinb, kw);

    attn_kernel<<<dim3(S_ / QT, NH, B_), 256, ATTN_SMEM>>>(q, k, v, gate, attn);

    split3<<<dim3(QDIM / 256, MTOT), blk>>>(attn, ab, QDIM, 1);
    hgemm_nt<<<dim3(HIDDEN_ / 128, MTOT / 128), blk>>>(ab, wob, out, MTOT, HIDDEN_, 3 * QDIM);
}